// round 1
// baseline (speedup 1.0000x reference)
#include <cuda_runtime.h>
#include <cstdint>

// adder2d: out[b,f,l] = -sum_{c,kh,kw} |W[f,c,kh,kw] - xpad[b,c,h+kh-1,w+kw-1]|
// B=16, C=128, H=W=28, F=128, KS=3, pad=1, stride=1.

#define BATCH   16
#define CIN     128
#define HW      28
#define LSP     784      // 28*28
#define FOUT    128
#define PADW    30       // padded tile side
#define CC      4        // channels per smem chunk
#define NCHUNK  (CIN / CC)   // 32
#define TFP     2        // filter pairs per CTA (=> 4 filters)
#define TL      7        // spatial outputs per thread
#define NT      112      // threads per CTA (112*7 = 784)

// acc2 += | w2 - p2 |   (packed f32x2; d = p2*(-1) + w2; abs via 2x LOP3)
__device__ __forceinline__ void absdiff_acc(unsigned long long& acc,
                                            unsigned long long p2,
                                            unsigned long long neg1,
                                            unsigned long long w2) {
    asm("{\n\t"
        ".reg .b64 d;\n\t"
        ".reg .b32 lo, hi;\n\t"
        "fma.rn.f32x2 d, %1, %2, %3;\n\t"
        "mov.b64 {lo, hi}, d;\n\t"
        "and.b32 lo, lo, 0x7fffffff;\n\t"
        "and.b32 hi, hi, 0x7fffffff;\n\t"
        "mov.b64 d, {lo, hi};\n\t"
        "add.rn.f32x2 %0, %0, d;\n\t"
        "}"
        : "+l"(acc)
        : "l"(p2), "l"(neg1), "l"(w2));
}

__global__ __launch_bounds__(NT)
void adder2d_kernel(const float* __restrict__ x,
                    const float* __restrict__ Wt,
                    float* __restrict__ out) {
    // x tile, duplicated (v,v) per value, zero halo. CC*900*8 = 28800 B
    __shared__ float2 xs[CC][PADW * PADW];
    // W pairs: ws[cc*9+kk][fp] = (W[f0], W[f0+1]) for f0 = fbase + 2*fp. 576 B
    __shared__ float2 ws[CC * 9][TFP];

    const int b     = blockIdx.y;
    const int fbase = blockIdx.x * (2 * TFP);
    const int t     = threadIdx.x;

    // zero whole xs (halo stays zero forever; interior rewritten per chunk)
    for (int i = t; i < CC * PADW * PADW; i += NT)
        (&xs[0][0])[i] = make_float2(0.f, 0.f);

    // spatial positions: l_j = t + 112*j  (lane-contiguous => coalesced)
    int offs[TL];
#pragma unroll
    for (int j = 0; j < TL; ++j) {
        int l = t + NT * j;
        int h = l / HW;
        int w = l - h * HW;
        offs[j] = (h + 1) * PADW + (w + 1);
    }

    unsigned long long acc[TFP][TL];
#pragma unroll
    for (int fp = 0; fp < TFP; ++fp)
#pragma unroll
        for (int j = 0; j < TL; ++j) acc[fp][j] = 0ull;  // packed (+0,+0)

    const unsigned long long NEG1 = 0xBF800000BF800000ull;  // (-1.f, -1.f)
    const float* xb = x + (size_t)b * CIN * LSP;

    __syncthreads();  // zeroing visible before first fill

#pragma unroll 1
    for (int ch = 0; ch < NCHUNK; ++ch) {
        // ---- fill x tile interior (duplicated) ----
#pragma unroll
        for (int ccc = 0; ccc < CC; ++ccc) {
            const float* xc = xb + (size_t)(ch * CC + ccc) * LSP;
#pragma unroll
            for (int j = 0; j < TL; ++j) {
                float v = xc[t + NT * j];
                xs[ccc][offs[j]] = make_float2(v, v);
            }
        }
        // ---- fill W pairs: CC*9*TFP = 72 entries ----
        for (int i = t; i < CC * 9 * TFP; i += NT) {
            int fp  = i % TFP;
            int k   = i / TFP;      // k = ccc*9 + kk
            int c   = ch * CC + (k / 9);
            int kk  = k % 9;
            int f0  = fbase + 2 * fp;
            const float* wp = Wt + ((size_t)f0 * CIN + c) * 9 + kk;
            ws[k][fp] = make_float2(wp[0], wp[CIN * 9]);
        }
        __syncthreads();

        // ---- compute ----
#pragma unroll 1
        for (int ccc = 0; ccc < CC; ++ccc) {
#pragma unroll
            for (int kk = 0; kk < 9; ++kk) {
                const int kh = kk / 3, kw = kk % 3;
                const int d  = (kh - 1) * PADW + (kw - 1);
                unsigned long long w2a =
                    *reinterpret_cast<const unsigned long long*>(&ws[ccc * 9 + kk][0]);
                unsigned long long w2b =
                    *reinterpret_cast<const unsigned long long*>(&ws[ccc * 9 + kk][1]);
#pragma unroll
                for (int j = 0; j < TL; ++j) {
                    unsigned long long p2 =
                        *reinterpret_cast<const unsigned long long*>(&xs[ccc][offs[j] + d]);
                    absdiff_acc(acc[0][j], p2, NEG1, w2a);
                    absdiff_acc(acc[1][j], p2, NEG1, w2b);
                }
            }
        }
        __syncthreads();
    }

    // ---- write output: negate each packed half ----
#pragma unroll
    for (int fp = 0; fp < TFP; ++fp) {
        int f0 = fbase + 2 * fp;
        float* o0 = out + ((size_t)b * FOUT + f0) * LSP;
        float* o1 = o0 + LSP;
#pragma unroll
        for (int j = 0; j < TL; ++j) {
            unsigned int lo = (unsigned int)(acc[fp][j] & 0xffffffffu);
            unsigned int hi = (unsigned int)(acc[fp][j] >> 32);
            o0[t + NT * j] = -__uint_as_float(lo);
            o1[t + NT * j] = -__uint_as_float(hi);
        }
    }
}

extern "C" void kernel_launch(void* const* d_in, const int* in_sizes, int n_in,
                              void* d_out, int out_size) {
    const float* x = (const float*)d_in[0];
    const float* W = (const float*)d_in[1];
    // safety: metadata order is (x, W); swap if sizes indicate otherwise
    if (n_in >= 2 && in_sizes[0] == FOUT * CIN * 9 && in_sizes[1] == BATCH * CIN * LSP) {
        const float* tmp = x; x = W; W = tmp;
    }
    float* out = (float*)d_out;

    dim3 grid(FOUT / (2 * TFP), BATCH);  // 32 x 16 = 512 CTAs
    dim3 block(NT);
    adder2d_kernel<<<grid, block>>>(x, W, out);
}

// round 2
// speedup vs baseline: 1.1989x; 1.1989x over previous
#include <cuda_runtime.h>
#include <cstdint>

// adder2d: out[b,f,l] = -sum_{c,kh,kw} |W[f,c,kh,kw] - xpad[b,c,...]|
// B=16, C=128, H=W=28, F=128, KS=3, pad=1, stride=1.
// Decomposition: grid (32 fgroups x 16 batches x 2 channel-halves) = 1024 CTAs.
// Each CTA: 4 filters (2 packed pairs), all 784 outputs, 64 channels.
// Packed f32x2 math: lanes = filter pairs, x duplicated (v,v).
// x tile: double-buffered, 1 channel per buffer, row stride 36 (conflict-free).
// Partials combined via atomicAdd (2 addends -> commutative -> deterministic).

#define BATCH 16
#define CIN   128
#define HW    28
#define LSP   784
#define FOUT  128
#define NT    112
#define TFP   2
#define CPC   64          // channels per CTA
#define SROW  36          // tile row stride (elements); 36 % 16 == 4 -> conflict-free
#define TROWS 30

typedef unsigned long long u64;
typedef unsigned int u32;

// acc2 += | w2 - p2 |   (packed f32x2)
__device__ __forceinline__ void absdiff_acc(u64& acc, u64 p2, u64 neg1, u64 w2) {
    asm("{\n\t"
        ".reg .b64 d;\n\t"
        ".reg .b32 lo, hi;\n\t"
        "fma.rn.f32x2 d, %1, %2, %3;\n\t"
        "mov.b64 {lo, hi}, d;\n\t"
        "and.b32 lo, lo, 0x7fffffff;\n\t"
        "and.b32 hi, hi, 0x7fffffff;\n\t"
        "mov.b64 d, {lo, hi};\n\t"
        "add.rn.f32x2 %0, %0, d;\n\t"
        "}"
        : "+l"(acc) : "l"(p2), "l"(neg1), "l"(w2));
}

__global__ void zero_out_kernel(float4* o) {
    o[(size_t)blockIdx.x * 1024 + threadIdx.x] = make_float4(0.f, 0.f, 0.f, 0.f);
}

__global__ __launch_bounds__(NT, 7)
void adder2d_kernel(const float* __restrict__ x,
                    const float* __restrict__ Wt,
                    float* __restrict__ out) {
    __shared__ u64    xs[2][TROWS * SROW];          // dup (v,v) tiles, 17280 B
    __shared__ float2 ws[CPC * 9 * TFP];            // (w_f0, w_f1) pairs, 9216 B

    const int b     = blockIdx.y;
    const int fbase = blockIdx.x * (2 * TFP);       // 4 filters per CTA
    const int chalf = blockIdx.z;                   // channel half
    const int t     = threadIdx.x;
    const int h     = t >> 2;                       // output row 0..27
    const int q     = t & 3;                        // col group: cols 7q..7q+6

    // zero both tiles (halo stays zero; interior rewritten per channel)
    for (int i = t; i < 2 * TROWS * SROW; i += NT)
        (&xs[0][0])[i] = 0ull;

    // stage all W for this CTA's 64 channels x 2 filter-pairs
    {
        const float* Wb = Wt + (size_t)fbase * (CIN * 9) + (size_t)chalf * CPC * 9;
        for (int i = t; i < CPC * 9 * TFP; i += NT) {
            int fp = i & 1;
            int k  = i >> 1;                        // c*9 + kk
            const float* wp = Wb + (size_t)(2 * fp) * (CIN * 9) + k;
            ws[i] = make_float2(wp[0], wp[CIN * 9]);
        }
    }

    // STS offsets for the fill (thread t writes l = t + 112*j)
    int offs_sts[7];
#pragma unroll
    for (int j = 0; j < 7; ++j) {
        int l  = t + NT * j;
        int hh = l / HW;
        int ww = l - hh * HW;
        offs_sts[j] = (hh + 1) * SROW + (ww + 1);
    }

    const float* xg = x + ((size_t)b * CIN + (size_t)chalf * CPC) * LSP;
    float r[7];
#pragma unroll
    for (int j = 0; j < 7; ++j) r[j] = xg[t + NT * j];   // prefetch channel 0

    u64 acc[TFP][7];
#pragma unroll
    for (int fp = 0; fp < TFP; ++fp)
#pragma unroll
        for (int j = 0; j < 7; ++j) acc[fp][j] = 0ull;

    const u64 NEG1 = 0xBF800000BF800000ull;
    const int cb   = h * SROW + 7 * q;   // tap base: (h+kh)*SROW + 7q + (j+kw)

    __syncthreads();   // zeroing + ws visible

#pragma unroll 1
    for (int ch = 0; ch < CPC; ++ch) {
        const int buf = ch & 1;
        // store current channel (duplicated)
#pragma unroll
        for (int j = 0; j < 7; ++j) {
            u32 u = __float_as_uint(r[j]);
            xs[buf][offs_sts[j]] = ((u64)u << 32) | (u64)u;
        }
        // prefetch next channel
        if (ch + 1 < CPC) {
            const float* xn = xg + (size_t)(ch + 1) * LSP;
#pragma unroll
            for (int j = 0; j < 7; ++j) r[j] = xn[t + NT * j];
        }
        __syncthreads();

        const float2* wrow = ws + ch * 18;   // (kk)*2 + fp
#pragma unroll
        for (int kh = 0; kh < 3; ++kh) {
            u64 xv[9];
#pragma unroll
            for (int i = 0; i < 9; ++i)
                xv[i] = xs[buf][cb + kh * SROW + i];
#pragma unroll
            for (int kw = 0; kw < 3; ++kw) {
                u64 w2a = *reinterpret_cast<const u64*>(&wrow[(kh * 3 + kw) * 2 + 0]);
                u64 w2b = *reinterpret_cast<const u64*>(&wrow[(kh * 3 + kw) * 2 + 1]);
#pragma unroll
                for (int j = 0; j < 7; ++j) {
                    absdiff_acc(acc[0][j], xv[j + kw], NEG1, w2a);
                    absdiff_acc(acc[1][j], xv[j + kw], NEG1, w2b);
                }
            }
        }
    }

    // epilogue: atomic-accumulate negated partials (2 contributions per output)
    float* ob = out + ((size_t)b * FOUT + fbase) * LSP + h * HW + 7 * q;
#pragma unroll
    for (int fp = 0; fp < TFP; ++fp) {
#pragma unroll
        for (int half = 0; half < 2; ++half) {
            float* o = ob + (size_t)(2 * fp + half) * LSP;
#pragma unroll
            for (int j = 0; j < 7; ++j) {
                u32 bits = half ? (u32)(acc[fp][j] >> 32) : (u32)(acc[fp][j] & 0xffffffffu);
                atomicAdd(&o[j], -__uint_as_float(bits));
            }
        }
    }
}

extern "C" void kernel_launch(void* const* d_in, const int* in_sizes, int n_in,
                              void* d_out, int out_size) {
    const float* x = (const float*)d_in[0];
    const float* W = (const float*)d_in[1];
    if (n_in >= 2 && in_sizes[0] == FOUT * CIN * 9 && in_sizes[1] == BATCH * CIN * LSP) {
        const float* tmp = x; x = W; W = tmp;
    }
    float* out = (float*)d_out;

    // out_size = 16*128*784 = 1,605,632 floats = 401,408 float4 = 392*1024
    zero_out_kernel<<<392, 1024>>>((float4*)out);

    dim3 grid(FOUT / (2 * TFP), BATCH, 2);   // 32 x 16 x 2 = 1024 CTAs
    adder2d_kernel<<<grid, NT>>>(x, W, out);
}

// round 3
// speedup vs baseline: 1.2883x; 1.0746x over previous
#include <cuda_runtime.h>
#include <cstdint>

// adder2d: out[b,f,l] = -sum_{c,kh,kw} |W[f,c,kh,kw] - xpad[b,c,...]|
// B=16, C=128, H=W=28, F=128, KS=3, pad=1, stride=1.
// Grid: 16 fgroups(8 filters) x 16 batches x 4 channel-quarters = 1024 CTAs.
// CTA: 224 threads (7 full warps). Threads t<112 handle filter pairs {0,1},
// t>=112 handle pairs {2,3}; each thread 7 spatial outputs x 2 packed pairs.
// Packed f32x2 math, abs via and.b64 (2x LOP3, no pack/unpack MOVs).
// x tile double-buffered, row stride 36 u64 (conflict-free), shared by all 8 filters.
// 4 channel-quarter partials combined via atomicAdd (tol 1e-3 >> fp reorder noise).

#define BATCH 16
#define CIN   128
#define HW    28
#define LSP   784
#define FOUT  128
#define NT    224
#define CPC   32          // channels per CTA
#define NCHQ  4           // channel quarters
#define SROW  36          // u64 row stride of tile
#define TROWS 30

typedef unsigned long long u64;
typedef unsigned int u32;

// acc2 += | w2 - p2 |  (packed f32x2; abs via 64-bit AND -> 2 LOP3, no movs)
__device__ __forceinline__ void absdiff_acc(u64& acc, u64 p2, u64 neg1, u64 w2) {
    asm("{\n\t"
        ".reg .b64 d;\n\t"
        "fma.rn.f32x2 d, %1, %2, %3;\n\t"
        "and.b64 d, d, 0x7FFFFFFF7FFFFFFF;\n\t"
        "add.rn.f32x2 %0, %0, d;\n\t"
        "}"
        : "+l"(acc) : "l"(p2), "l"(neg1), "l"(w2));
}

__global__ void zero_out_kernel(float4* o) {
    o[(size_t)blockIdx.x * 1024 + threadIdx.x] = make_float4(0.f, 0.f, 0.f, 0.f);
}

__global__ __launch_bounds__(NT, 4)
void adder2d_kernel(const float* __restrict__ x,
                    const float* __restrict__ Wt,
                    float* __restrict__ out) {
    __shared__ u64    xs[2][TROWS * SROW];   // dup (v,v) tiles, 17280 B
    __shared__ float2 ws[CPC * 9 * 4];       // [c][kk][pair] -> (w_f0, w_f1), 9216 B

    const int b     = blockIdx.y;
    const int fbase = blockIdx.x * 8;        // 8 filters per CTA
    const int cq    = blockIdx.z;            // channel quarter
    const int t     = threadIdx.x;
    const int tl    = (t < 112) ? t : (t - 112);
    const int g     = (t < 112) ? 0 : 2;     // pair-group base (pairs g, g+1)
    const int h     = tl >> 2;               // output row 0..27
    const int q     = tl & 3;                // col group: cols 7q..7q+6

    // zero both tiles (halo stays zero; interior rewritten per channel)
    for (int i = t; i < 2 * TROWS * SROW; i += NT)
        (&xs[0][0])[i] = 0ull;

    // stage W pairs for 8 filters x 32 channels: 1152 float2 entries
    {
        const float* Wb = Wt + (size_t)fbase * (CIN * 9) + (size_t)cq * CPC * 9;
        for (int i = t; i < CPC * 9 * 4; i += NT) {
            int p   = i & 3;          // pair 0..3
            int kkc = i >> 2;         // c*9 + kk
            const float* wp = Wb + (size_t)(2 * p) * (CIN * 9) + kkc;
            ws[kkc * 4 + p] = make_float2(wp[0], wp[CIN * 9]);
        }
    }

    // fill mapping: thread t stores l = t + 224*j, j=0..2; plus j=3 for t<112
    int offs_sts[4];
#pragma unroll
    for (int j = 0; j < 4; ++j) {
        int l = t + NT * j;
        if (l < LSP) {
            int hh = l / HW;
            int ww = l - hh * HW;
            offs_sts[j] = (hh + 1) * SROW + (ww + 1);
        } else offs_sts[j] = 0;
    }

    const float* xg = x + ((size_t)b * CIN + (size_t)cq * CPC) * LSP;
    float r[4];
#pragma unroll
    for (int j = 0; j < 3; ++j) r[j] = xg[t + NT * j];
    if (t < 112) r[3] = xg[t + NT * 3];

    u64 acc[2][7];
#pragma unroll
    for (int fp = 0; fp < 2; ++fp)
#pragma unroll
        for (int j = 0; j < 7; ++j) acc[fp][j] = 0ull;

    const u64 NEG1 = 0xBF800000BF800000ull;  // (-1.f, -1.f)
    const int cb   = h * SROW + 7 * q;

    __syncthreads();  // zeroing + ws visible

#define STEP(CH, BUF)                                                          \
    {                                                                          \
        _Pragma("unroll")                                                      \
        for (int j = 0; j < 3; ++j) {                                          \
            u32 u = __float_as_uint(r[j]);                                     \
            xs[BUF][offs_sts[j]] = ((u64)u << 32) | (u64)u;                    \
        }                                                                      \
        if (t < 112) {                                                         \
            u32 u = __float_as_uint(r[3]);                                     \
            xs[BUF][offs_sts[3]] = ((u64)u << 32) | (u64)u;                    \
        }                                                                      \
        if ((CH) + 1 < CPC) {                                                  \
            const float* xn = xg + (size_t)((CH) + 1) * LSP;                   \
            _Pragma("unroll")                                                  \
            for (int j = 0; j < 3; ++j) r[j] = xn[t + NT * j];                 \
            if (t < 112) r[3] = xn[t + NT * 3];                                \
        }                                                                      \
        __syncthreads();                                                       \
        const float2* wrow = ws + (CH) * 36;                                   \
        _Pragma("unroll")                                                      \
        for (int kh = 0; kh < 3; ++kh) {                                       \
            u64 xv[9];                                                         \
            _Pragma("unroll")                                                  \
            for (int i = 0; i < 9; ++i)                                        \
                xv[i] = xs[BUF][cb + kh * SROW + i];                           \
            _Pragma("unroll")                                                  \
            for (int kw = 0; kw < 3; ++kw) {                                   \
                ulonglong2 wv = *reinterpret_cast<const ulonglong2*>(          \
                    &wrow[(kh * 3 + kw) * 4 + g]);                             \
                _Pragma("unroll")                                              \
                for (int j = 0; j < 7; ++j) {                                  \
                    absdiff_acc(acc[0][j], xv[j + kw], NEG1, wv.x);            \
                    absdiff_acc(acc[1][j], xv[j + kw], NEG1, wv.y);            \
                }                                                              \
            }                                                                  \
        }                                                                      \
    }

#pragma unroll 1
    for (int ch = 0; ch < CPC; ch += 2) {
        STEP(ch, 0)
        STEP(ch + 1, 1)
    }
#undef STEP

    // epilogue: atomic-accumulate negated partials (4 contributions/output)
    float* ob = out + ((size_t)b * FOUT + fbase) * LSP + h * HW + 7 * q;
#pragma unroll
    for (int fp = 0; fp < 2; ++fp) {
        int f0 = 2 * (g + fp);
#pragma unroll
        for (int half = 0; half < 2; ++half) {
            float* o = ob + (size_t)(f0 + half) * LSP;
#pragma unroll
            for (int j = 0; j < 7; ++j) {
                u32 bits = half ? (u32)(acc[fp][j] >> 32)
                                : (u32)(acc[fp][j] & 0xffffffffu);
                atomicAdd(&o[j], -__uint_as_float(bits));
            }
        }
    }
}

extern "C" void kernel_launch(void* const* d_in, const int* in_sizes, int n_in,
                              void* d_out, int out_size) {
    const float* x = (const float*)d_in[0];
    const float* W = (const float*)d_in[1];
    if (n_in >= 2 && in_sizes[0] == FOUT * CIN * 9 && in_sizes[1] == BATCH * CIN * LSP) {
        const float* tmp = x; x = W; W = tmp;
    }
    float* out = (float*)d_out;

    // out = 16*128*784 floats = 401408 float4 = 392 * 1024
    zero_out_kernel<<<392, 1024>>>((float4*)out);

    dim3 grid(FOUT / 8, BATCH, NCHQ);  // 16 x 16 x 4 = 1024 CTAs
    adder2d_kernel<<<grid, NT>>>(x, W, out);
}